// round 1
// baseline (speedup 1.0000x reference)
#include <cuda_runtime.h>

#define BB 2
#define SS 2048
#define HH 4096
#define NHH 32
#define HDD 128
#define INV_NORM 0.088388347648318447f   // 1/sqrt(128)

// ---------------- scratch (allocation-free rule: __device__ globals) ----------------
__device__ float g_q[16777216];    // [B,NH,S,HD]  (pre-scaled by INV_NORM)
__device__ float g_k[16777216];    // [B,NH,S,HD]
__device__ float g_v[16777216];    // [B,NH,S,HD]
__device__ float g_ctx[16777216];  // [B,S,H] (heads merged)

// =====================================================================
// Tiled fp32 GEMM: C[m,n] = A[m,:] . W[n,:]  (both K-contiguous)
// BM=BN=128, BK=16, 256 threads, 8x8 per thread, 2 CTAs/SM.
// MODE 0: A = hidden, scatter (+bias) into g_q/g_k/g_v (q scaled by INV_NORM)
// MODE 1: A = g_ctx,  out = acc + bias + residual
// =====================================================================
template<int MODE>
__global__ __launch_bounds__(256, 2) void gemm_kernel(
    const float* __restrict__ Ain, const float* __restrict__ W,
    const float* __restrict__ bias, const float* __restrict__ residual,
    float* __restrict__ out)
{
    __shared__ float As[16][128];
    __shared__ float Bs[16][128];

    const float* A = (MODE == 0) ? Ain : (const float*)g_ctx;

    const int bm = blockIdx.y * 128;
    const int bn = blockIdx.x * 128;
    const int tid = threadIdx.x;
    const int tx = tid & 15;      // 0..15  -> 8 cols
    const int ty = tid >> 4;      // 0..15  -> 8 rows
    const int lr = tid >> 2;      // 0..63  load row
    const int lc = (tid & 3) << 2;// 0,4,8,12 load col base

    const float* Ap = A + (size_t)(bm + lr) * HH + lc;
    const float* Wp = W + (size_t)(bn + lr) * HH + lc;

    float acc[8][8];
#pragma unroll
    for (int i = 0; i < 8; i++)
#pragma unroll
        for (int j = 0; j < 8; j++) acc[i][j] = 0.0f;

    for (int k0 = 0; k0 < HH; k0 += 16) {
        float4 a0 = *(const float4*)(Ap + k0);
        float4 a1 = *(const float4*)(Ap + (size_t)64 * HH + k0);
        float4 b0 = *(const float4*)(Wp + k0);
        float4 b1 = *(const float4*)(Wp + (size_t)64 * HH + k0);

        As[lc + 0][lr] = a0.x; As[lc + 1][lr] = a0.y; As[lc + 2][lr] = a0.z; As[lc + 3][lr] = a0.w;
        As[lc + 0][lr + 64] = a1.x; As[lc + 1][lr + 64] = a1.y; As[lc + 2][lr + 64] = a1.z; As[lc + 3][lr + 64] = a1.w;
        Bs[lc + 0][lr] = b0.x; Bs[lc + 1][lr] = b0.y; Bs[lc + 2][lr] = b0.z; Bs[lc + 3][lr] = b0.w;
        Bs[lc + 0][lr + 64] = b1.x; Bs[lc + 1][lr + 64] = b1.y; Bs[lc + 2][lr + 64] = b1.z; Bs[lc + 3][lr + 64] = b1.w;
        __syncthreads();

#pragma unroll
        for (int kk = 0; kk < 16; kk++) {
            float4 ar0 = *(const float4*)(&As[kk][ty * 8]);
            float4 ar1 = *(const float4*)(&As[kk][ty * 8 + 4]);
            float4 br0 = *(const float4*)(&Bs[kk][tx * 8]);
            float4 br1 = *(const float4*)(&Bs[kk][tx * 8 + 4]);
            float ar[8] = {ar0.x, ar0.y, ar0.z, ar0.w, ar1.x, ar1.y, ar1.z, ar1.w};
            float br[8] = {br0.x, br0.y, br0.z, br0.w, br1.x, br1.y, br1.z, br1.w};
#pragma unroll
            for (int i = 0; i < 8; i++)
#pragma unroll
                for (int j = 0; j < 8; j++)
                    acc[i][j] = fmaf(ar[i], br[j], acc[i][j]);
        }
        __syncthreads();
    }

    // ---------------- epilogue ----------------
#pragma unroll
    for (int i = 0; i < 8; i++) {
        const int m = bm + ty * 8 + i;
#pragma unroll
        for (int j = 0; j < 8; j++) {
            const int n = bn + tx * 8 + j;
            float val = acc[i][j] + bias[n];
            if (MODE == 0) {
                const int b_ = m >> 11;        // / S
                const int s_ = m & 2047;       // % S
                const int nh = n / 384;        // n / (3*HD)
                const int rem = n - nh * 384;
                const int which = rem >> 7;    // / HD
                const int d = rem & 127;       // % HD
                const size_t idx = ((size_t)(b_ * NHH + nh) * SS + s_) * HDD + d;
                if (which == 0)      g_q[idx] = val * INV_NORM;
                else if (which == 1) g_k[idx] = val;
                else                 g_v[idx] = val;
            } else {
                const size_t idx = (size_t)m * HH + n;
                out[idx] = val + residual[idx];
            }
        }
    }
}

// =====================================================================
// Causal flash attention with ALiBi.
// Grid: (S/64, B*NH). 256 threads = 8 warps.
// Each CTA: 64 q-rows. k processed in blocks of 128 up to the diagonal.
// Warp w owns q-rows w*8..w*8+7 entirely -> softmax row reductions are
// plain full-warp butterflies. Column mapping c = 32*j + lane with
// stride-129 smem makes all inner LDS conflict-free or broadcast.
// =====================================================================
#define QST 129
#define KST 129
#define VST 132
#define PST 132
#define ATT_SMEM ((64 * QST + 128 * KST + 128 * VST + 64 * PST + 128) * 4)

__global__ __launch_bounds__(256) void attn_kernel(const float* __restrict__ alibi)
{
    extern __shared__ float sm[];
    float* Qs = sm;                  // [64][129]
    float* Ks = Qs + 64 * QST;       // [128][129]
    float* Vs = Ks + 128 * KST;      // [128][132]
    float* Ps = Vs + 128 * VST;      // [64][132]
    float* al = Ps + 64 * PST;       // [128]

    const int qb = blockIdx.x;       // 0..31
    const int bh = blockIdx.y;       // 0..63
    const int b_ = bh >> 5;
    const int nh = bh & 31;
    const int tid = threadIdx.x;
    const int lane = tid & 31;       // column slot
    const int wrp  = tid >> 5;       // row group (8 rows)

    const float* Qg = g_q + ((size_t)bh * SS + qb * 64) * HDD;
    const float* Kg = g_k + (size_t)bh * SS * HDD;
    const float* Vg = g_v + (size_t)bh * SS * HDD;

    // load Q tile (64 x 128)
    for (int t = tid; t < 64 * 32; t += 256) {
        const int r = t >> 5;
        const int c = (t & 31) << 2;
        float4 qv = *(const float4*)(Qg + r * HDD + c);
        Qs[r * QST + c + 0] = qv.x; Qs[r * QST + c + 1] = qv.y;
        Qs[r * QST + c + 2] = qv.z; Qs[r * QST + c + 3] = qv.w;
    }

    float m_run[8], l_run[8], o[8][4];
#pragma unroll
    for (int i = 0; i < 8; i++) {
        m_run[i] = -1e30f; l_run[i] = 0.0f;
#pragma unroll
        for (int j = 0; j < 4; j++) o[i][j] = 0.0f;
    }

    const int kb_max = (qb * 64 + 63) >> 7;
    for (int kb = 0; kb <= kb_max; kb++) {
        __syncthreads();  // prev PV done (and Q tile ready on first iter)

        // fill K,V tiles (128 x 128 each) + alibi
        const float* kgp = Kg + (size_t)(kb * 128) * HDD;
        const float* vgp = Vg + (size_t)(kb * 128) * HDD;
        for (int t = tid; t < 128 * 32; t += 256) {
            const int r = t >> 5;
            const int c = (t & 31) << 2;
            float4 kv = *(const float4*)(kgp + r * HDD + c);
            Ks[r * KST + c + 0] = kv.x; Ks[r * KST + c + 1] = kv.y;
            Ks[r * KST + c + 2] = kv.z; Ks[r * KST + c + 3] = kv.w;
            float4 vv = *(const float4*)(vgp + r * HDD + c);
            *(float4*)(Vs + r * VST + c) = vv;
        }
        if (tid < 128) al[tid] = alibi[(size_t)bh * SS + kb * 128 + tid];
        __syncthreads();

        // ---- QK^T : rows wrp*8+i, cols 32*j+lane ----
        float sc[8][4];
#pragma unroll
        for (int i = 0; i < 8; i++)
#pragma unroll
            for (int j = 0; j < 4; j++) sc[i][j] = 0.0f;

#pragma unroll 4
        for (int d = 0; d < HDD; d++) {
            float a[8], bv[4];
#pragma unroll
            for (int i = 0; i < 8; i++) a[i] = Qs[(wrp * 8 + i) * QST + d];   // broadcast
#pragma unroll
            for (int j = 0; j < 4; j++) bv[j] = Ks[(32 * j + lane) * KST + d]; // conflict-free
#pragma unroll
            for (int i = 0; i < 8; i++)
#pragma unroll
                for (int j = 0; j < 4; j++)
                    sc[i][j] = fmaf(a[i], bv[j], sc[i][j]);
        }

        // alibi + causal mask
        const int qg0 = qb * 64 + wrp * 8;
        const int kg_base = kb * 128;
        float alv[4];
#pragma unroll
        for (int j = 0; j < 4; j++) alv[j] = al[32 * j + lane];
#pragma unroll
        for (int i = 0; i < 8; i++) {
            const int qg = qg0 + i;
#pragma unroll
            for (int j = 0; j < 4; j++) {
                const int kg = kg_base + 32 * j + lane;
                const float sv = sc[i][j] + alv[j];
                sc[i][j] = (kg > qg) ? -1e30f : sv;
            }
        }

        // ---- online softmax per row (full-warp reductions) ----
#pragma unroll
        for (int i = 0; i < 8; i++) {
            float mx = fmaxf(fmaxf(sc[i][0], sc[i][1]), fmaxf(sc[i][2], sc[i][3]));
#pragma unroll
            for (int off = 16; off >= 1; off >>= 1)
                mx = fmaxf(mx, __shfl_xor_sync(0xffffffffu, mx, off));
            const float mnew = fmaxf(m_run[i], mx);
            const float alpha = __expf(m_run[i] - mnew);
            float ls = 0.0f;
#pragma unroll
            for (int j = 0; j < 4; j++) {
                const float p = __expf(sc[i][j] - mnew);
                sc[i][j] = p;
                ls += p;
            }
#pragma unroll
            for (int off = 16; off >= 1; off >>= 1)
                ls += __shfl_xor_sync(0xffffffffu, ls, off);
            l_run[i] = l_run[i] * alpha + ls;
            m_run[i] = mnew;
#pragma unroll
            for (int j = 0; j < 4; j++) o[i][j] *= alpha;
#pragma unroll
            for (int j = 0; j < 4; j++)
                Ps[(wrp * 8 + i) * PST + 32 * j + lane] = sc[i][j];
        }
        __syncthreads();

        // ---- P @ V : rows wrp*8+i, d = 32*j+lane ----
#pragma unroll 4
        for (int kc = 0; kc < 128; kc++) {
            float p[8], vv[4];
#pragma unroll
            for (int i = 0; i < 8; i++) p[i] = Ps[(wrp * 8 + i) * PST + kc];   // broadcast
#pragma unroll
            for (int j = 0; j < 4; j++) vv[j] = Vs[kc * VST + 32 * j + lane];  // conflict-free
#pragma unroll
            for (int i = 0; i < 8; i++)
#pragma unroll
                for (int j = 0; j < 4; j++)
                    o[i][j] = fmaf(p[i], vv[j], o[i][j]);
        }
    }

    // write ctx[b][s][nh*HD + d]  (heads merged, coalesced over lane)
#pragma unroll
    for (int i = 0; i < 8; i++) {
        const int s_ = qb * 64 + wrp * 8 + i;
        const float invl = 1.0f / l_run[i];
        float* op = g_ctx + ((size_t)b_ * SS + s_) * HH + nh * HDD;
#pragma unroll
        for (int j = 0; j < 4; j++)
            op[32 * j + lane] = o[i][j] * invl;
    }
}

// =====================================================================
extern "C" void kernel_launch(void* const* d_in, const int* in_sizes, int n_in,
                              void* d_out, int out_size)
{
    (void)in_sizes; (void)n_in; (void)out_size;
    const float* hidden   = (const float*)d_in[0];
    const float* residual = (const float*)d_in[1];
    const float* alibi    = (const float*)d_in[2];
    // d_in[3] = attention_mask (deterministic causal; handled analytically)
    const float* W_qkv    = (const float*)d_in[4];
    const float* b_qkv    = (const float*)d_in[5];
    const float* W_dense  = (const float*)d_in[6];
    const float* b_dense  = (const float*)d_in[7];
    float* out = (float*)d_out;

    cudaFuncSetAttribute(attn_kernel, cudaFuncAttributeMaxDynamicSharedMemorySize, ATT_SMEM);

    dim3 blk(256);
    // 1) QKV projection: M=4096, N=12288
    gemm_kernel<0><<<dim3(96, 32), blk>>>(hidden, W_qkv, b_qkv, nullptr, nullptr);
    // 2) causal flash attention with ALiBi
    attn_kernel<<<dim3(32, 64), blk, ATT_SMEM>>>(alibi);
    // 3) dense projection + residual: M=4096, N=4096
    gemm_kernel<1><<<dim3(32, 32), blk>>>(nullptr, W_dense, b_dense, residual, out);
}

// round 4
// speedup vs baseline: 1.6149x; 1.6149x over previous
#include <cuda_runtime.h>
#include <cuda_bf16.h>
#include <cstdint>

#define SS 2048
#define HH 4096
#define NHH 32
#define HDD 128
#define K2 8192
#define INV_NORM 0.088388347648318447f   // 1/sqrt(128)

// ---------------- scratch (__device__ globals; no allocs allowed) ----------------
__device__ float g_q[16777216];    // [B,NH,S,HD] (pre-scaled by INV_NORM)
__device__ float g_k[16777216];
__device__ float g_v[16777216];
__device__ float g_ctx[16777216];  // [B,S,H]
__device__ __nv_bfloat16 g_A2[(size_t)4096 * K2];    // hidden  [hi|lo]
__device__ __nv_bfloat16 g_W2[(size_t)12288 * K2];   // W_qkv   [hi|lo]
__device__ __nv_bfloat16 g_Wd2[(size_t)4096 * K2];   // W_dense [hi|lo]
__device__ __nv_bfloat16 g_C2[(size_t)4096 * K2];    // ctx     [hi|lo]

// ---------------- PTX helpers ----------------
__device__ __forceinline__ uint32_t smem_u32(const void* p) {
    uint32_t a;
    asm("{ .reg .u64 t; cvta.to.shared.u64 t, %1; cvt.u32.u64 %0, t; }" : "=r"(a) : "l"(p));
    return a;
}
#define CP_ASYNC16(dst, src) \
    asm volatile("cp.async.cg.shared.global [%0], [%1], 16;" :: "r"(dst), "l"(src))
#define CP_COMMIT() asm volatile("cp.async.commit_group;" ::: "memory")
#define CP_WAIT1()  asm volatile("cp.async.wait_group 1;" ::: "memory")
#define CP_WAIT0()  asm volatile("cp.async.wait_group 0;" ::: "memory")

__device__ __forceinline__ void ldsm4(uint32_t* r, uint32_t addr) {
    asm volatile("ldmatrix.sync.aligned.m8n8.x4.shared.b16 {%0,%1,%2,%3}, [%4];"
        : "=r"(r[0]), "=r"(r[1]), "=r"(r[2]), "=r"(r[3]) : "r"(addr));
}
__device__ __forceinline__ void mma16816(float* c, const uint32_t* a, const uint32_t* b) {
    asm volatile(
        "mma.sync.aligned.m16n8k16.row.col.f32.bf16.bf16.f32 "
        "{%0,%1,%2,%3}, {%4,%5,%6,%7}, {%8,%9}, {%0,%1,%2,%3};"
        : "+f"(c[0]), "+f"(c[1]), "+f"(c[2]), "+f"(c[3])
        : "r"(a[0]), "r"(a[1]), "r"(a[2]), "r"(a[3]), "r"(b[0]), "r"(b[1]));
}

// ====================================================================
// fp32 [R][4096] -> bf16 [R][8192] as [hi | lo]
// ====================================================================
template<int WHICH>
__global__ void convert_kernel(const float* __restrict__ src) {
    size_t i = (size_t)blockIdx.x * 256 + threadIdx.x;  // one float4 per thread
    size_t r = i >> 10;
    int c = (int)(i & 1023) * 4;
    const float* sp = (WHICH == 3) ? (const float*)g_ctx : src;
    float4 v = *(const float4*)(sp + (r << 12) + c);
    float f[4] = {v.x, v.y, v.z, v.w};
    unsigned short h[4], l[4];
#pragma unroll
    for (int j = 0; j < 4; j++) {
        __nv_bfloat16 hb = __float2bfloat16(f[j]);
        __nv_bfloat16 lb = __float2bfloat16(f[j] - __bfloat162float(hb));
        h[j] = __bfloat16_as_ushort(hb);
        l[j] = __bfloat16_as_ushort(lb);
    }
    uint2 hp = make_uint2((uint32_t)h[0] | ((uint32_t)h[1] << 16),
                          (uint32_t)h[2] | ((uint32_t)h[3] << 16));
    uint2 lp = make_uint2((uint32_t)l[0] | ((uint32_t)l[1] << 16),
                          (uint32_t)l[2] | ((uint32_t)l[3] << 16));
    __nv_bfloat16* dst = (WHICH == 0) ? g_A2 : (WHICH == 1) ? g_W2 : (WHICH == 2) ? g_Wd2 : g_C2;
    __nv_bfloat16* base = dst + r * K2 + c;
    *(uint2*)(base) = hp;
    *(uint2*)(base + 4096) = lp;
}

// ====================================================================
// mma.sync bf16 GEMM with 3-term compensation via chunk remap.
// C[4096,N] = sum over 192 chunks of 64: A[ak]·W[wk]
//   c <  64 : hi·hi     (ak=c,     wk=c)
//   64..127 : lo·hi     (ak=c,     wk=c-64)
//   128..191: hi·lo     (ak=c-128, wk=c-64)
// BM=128,BN=128,BK=64; 8 warps, warp tile 64x32; cp.async double buffer.
// MODE 0: scatter (+bias) to g_q/g_k/g_v (q * INV_NORM)
// MODE 1: out = acc + bias + residual
// ====================================================================
#define ROWB 144                 // smem row stride bytes (64+8 bf16)
#define TILEB (128 * ROWB)       // 18432
#define GSM_TOTAL (4 * TILEB)    // 73728: buf0{A,B}, buf1{A,B}
#define NCH 192

__device__ __forceinline__ void load_chunk(uint32_t sbuf,
    const __nv_bfloat16* Abase, const __nv_bfloat16* Wbase,
    int ak, int wk, int tid)
{
    const int row = tid >> 1;
    const int half = tid & 1;
    const __nv_bfloat16* asrc = Abase + (size_t)row * K2 + ak * 64 + half * 32;
    const uint32_t adst = sbuf + row * ROWB + half * 64;
#pragma unroll
    for (int i = 0; i < 4; i++) CP_ASYNC16(adst + i * 16, asrc + i * 8);
    const __nv_bfloat16* wsrc = Wbase + (size_t)row * K2 + wk * 64 + half * 32;
    const uint32_t wdst = sbuf + TILEB + row * ROWB + half * 64;
#pragma unroll
    for (int i = 0; i < 4; i++) CP_ASYNC16(wdst + i * 16, wsrc + i * 8);
}

template<int MODE>
__global__ __launch_bounds__(256) void hgemm_kernel(
    const float* __restrict__ bias, const float* __restrict__ residual,
    float* __restrict__ out)
{
    extern __shared__ char smem[];
    const uint32_t sb = smem_u32(smem);
    const int tid = threadIdx.x;
    const int wid = tid >> 5;
    const int lane = tid & 31;
    const int wm = (wid >> 2) * 64;
    const int wn = (wid & 3) * 32;

    // supertiled rasterization: 16 M-tiles x 8 N-tiles per group
    const int id = blockIdx.x;
    const int g = id >> 7;
    const int inner = id & 127;
    const int mg = g & 1;                 // TILES_M = 32 -> 2 groups
    const int ng = g >> 1;
    const int bm = (mg * 16 + (inner & 15)) * 128;
    const int bn = (ng * 8 + (inner >> 4)) * 128;

    const __nv_bfloat16* Abase = ((MODE == 0) ? g_A2 : g_C2) + (size_t)bm * K2;
    const __nv_bfloat16* Wbase = ((MODE == 0) ? g_W2 : g_Wd2) + (size_t)bn * K2;

    float acc[4][4][4];
#pragma unroll
    for (int mt = 0; mt < 4; mt++)
#pragma unroll
        for (int nt = 0; nt < 4; nt++)
#pragma unroll
            for (int r = 0; r < 4; r++) acc[mt][nt][r] = 0.0f;

    // prologue: chunks 0,1
    load_chunk(sb, Abase, Wbase, 0, 0, tid); CP_COMMIT();
    load_chunk(sb + 2 * TILEB, Abase, Wbase, 1, 1, tid); CP_COMMIT();

#pragma unroll 1
    for (int c = 0; c < NCH; c++) {
        if (c == NCH - 1) { CP_WAIT0(); } else { CP_WAIT1(); }
        __syncthreads();

        const uint32_t abuf = sb + (c & 1) * 2 * TILEB;
        const uint32_t bbuf = abuf + TILEB;
#pragma unroll
        for (int ks = 0; ks < 4; ks++) {
            uint32_t afr[4][4], bfr[2][4];
#pragma unroll
            for (int mt = 0; mt < 4; mt++) {
                const uint32_t addr = abuf +
                    (wm + mt * 16 + ((lane >> 3) & 1) * 8 + (lane & 7)) * ROWB +
                    ks * 32 + ((lane >> 4) & 1) * 16;
                ldsm4(afr[mt], addr);
            }
#pragma unroll
            for (int bi = 0; bi < 2; bi++) {
                const uint32_t addr = bbuf +
                    (wn + bi * 16 + ((lane >> 4) & 1) * 8 + (lane & 7)) * ROWB +
                    ks * 32 + ((lane >> 3) & 1) * 16;
                ldsm4(bfr[bi], addr);
            }
#pragma unroll
            for (int mt = 0; mt < 4; mt++)
#pragma unroll
                for (int nt = 0; nt < 4; nt++)
                    mma16816(acc[mt][nt], afr[mt], &bfr[nt >> 1][(nt & 1) * 2]);
        }
        __syncthreads();

        const int cc = c + 2;
        if (cc < NCH) {
            const int ak = cc & 127;                 // hi for c<64 & c>=128; lo for 64..127
            const int wk = (cc < 64) ? cc : cc - 64; // hi for c<128; lo after
            load_chunk(sb + (c & 1) * 2 * TILEB, Abase, Wbase, ak, wk, tid);
            CP_COMMIT();
        }
    }

    // ---------------- epilogue ----------------
    const int gq = lane >> 2;       // row within m16
    const int tq = lane & 3;        // col pair within n8
    if (MODE == 0) {
        const int sec = (bn >> 7) % 3;
        const int nh = bn / 384;
        float* dstT = (sec == 0) ? g_q : (sec == 1) ? g_k : g_v;
        const float scale = (sec == 0) ? INV_NORM : 1.0f;
#pragma unroll
        for (int mt = 0; mt < 4; mt++) {
            const int m0 = bm + wm + mt * 16 + gq;
#pragma unroll
            for (int nt = 0; nt < 4; nt++) {
                const int d = wn + nt * 8 + tq * 2;
                const float2 bv = *(const float2*)(bias + bn + d);
                {
                    const int b_ = m0 >> 11, s_ = m0 & 2047;
                    float2 o0 = make_float2((acc[mt][nt][0] + bv.x) * scale,
                                            (acc[mt][nt][1] + bv.y) * scale);
                    *(float2*)(dstT + (((size_t)(b_ * NHH + nh) * SS + s_) << 7) + d) = o0;
                }
                {
                    const int m1 = m0 + 8;
                    const int b_ = m1 >> 11, s_ = m1 & 2047;
                    float2 o1 = make_float2((acc[mt][nt][2] + bv.x) * scale,
                                            (acc[mt][nt][3] + bv.y) * scale);
                    *(float2*)(dstT + (((size_t)(b_ * NHH + nh) * SS + s_) << 7) + d) = o1;
                }
            }
        }
    } else {
#pragma unroll
        for (int mt = 0; mt < 4; mt++) {
            const int m0 = bm + wm + mt * 16 + gq;
#pragma unroll
            for (int nt = 0; nt < 4; nt++) {
                const int n0 = bn + wn + nt * 8 + tq * 2;
                const float2 bv = *(const float2*)(bias + n0);
                {
                    const size_t i0 = (size_t)m0 * HH + n0;
                    const float2 rv = *(const float2*)(residual + i0);
                    *(float2*)(out + i0) = make_float2(acc[mt][nt][0] + bv.x + rv.x,
                                                       acc[mt][nt][1] + bv.y + rv.y);
                }
                {
                    const size_t i1 = (size_t)(m0 + 8) * HH + n0;
                    const float2 rv = *(const float2*)(residual + i1);
                    *(float2*)(out + i1) = make_float2(acc[mt][nt][2] + bv.x + rv.x,
                                                       acc[mt][nt][3] + bv.y + rv.y);
                }
            }
        }
    }
}

// ====================================================================
// Causal flash attention with ALiBi (unchanged — FFMA SIMT, known good).
// ====================================================================
#define QST 129
#define KST 129
#define VST 132
#define PST 132
#define ATT_SMEM ((64 * QST + 128 * KST + 128 * VST + 64 * PST + 128) * 4)

__global__ __launch_bounds__(256) void attn_kernel(const float* __restrict__ alibi)
{
    extern __shared__ float sm[];
    float* Qs = sm;
    float* Ks = Qs + 64 * QST;
    float* Vs = Ks + 128 * KST;
    float* Ps = Vs + 128 * VST;
    float* al = Ps + 64 * PST;

    const int qb = blockIdx.x;
    const int bh = blockIdx.y;
    const int b_ = bh >> 5;
    const int nh = bh & 31;
    const int tid = threadIdx.x;
    const int lane = tid & 31;
    const int wrp = tid >> 5;

    const float* Qg = g_q + ((size_t)bh * SS + qb * 64) * HDD;
    const float* Kg = g_k + (size_t)bh * SS * HDD;
    const float* Vg = g_v + (size_t)bh * SS * HDD;

    for (int t = tid; t < 64 * 32; t += 256) {
        const int r = t >> 5;
        const int c = (t & 31) << 2;
        float4 qv = *(const float4*)(Qg + r * HDD + c);
        Qs[r * QST + c + 0] = qv.x; Qs[r * QST + c + 1] = qv.y;
        Qs[r * QST + c + 2] = qv.z; Qs[r * QST + c + 3] = qv.w;
    }

    float m_run[8], l_run[8], o[8][4];
#pragma unroll
    for (int i = 0; i < 8; i++) {
        m_run[i] = -1e30f; l_run[i] = 0.0f;
#pragma unroll
        for (int j = 0; j < 4; j++) o[i][j] = 0.0f;
    }

    const int kb_max = (qb * 64 + 63) >> 7;
    for (int kb = 0; kb <= kb_max; kb++) {
        __syncthreads();
        const float* kgp = Kg + (size_t)(kb * 128) * HDD;
        const float* vgp = Vg + (size_t)(kb * 128) * HDD;
        for (int t = tid; t < 128 * 32; t += 256) {
            const int r = t >> 5;
            const int c = (t & 31) << 2;
            float4 kv = *(const float4*)(kgp + r * HDD + c);
            Ks[r * KST + c + 0] = kv.x; Ks[r * KST + c + 1] = kv.y;
            Ks[r * KST + c + 2] = kv.z; Ks[r * KST + c + 3] = kv.w;
            float4 vv = *(const float4*)(vgp + r * HDD + c);
            *(float4*)(Vs + r * VST + c) = vv;
        }
        if (tid < 128) al[tid] = alibi[(size_t)bh * SS + kb * 128 + tid];
        __syncthreads();

        float sc[8][4];
#pragma unroll
        for (int i = 0; i < 8; i++)
#pragma unroll
            for (int j = 0; j < 4; j++) sc[i][j] = 0.0f;

#pragma unroll 4
        for (int d = 0; d < HDD; d++) {
            float a[8], bv[4];
#pragma unroll
            for (int i = 0; i < 8; i++) a[i] = Qs[(wrp * 8 + i) * QST + d];
#pragma unroll
            for (int j = 0; j < 4; j++) bv[j] = Ks[(32 * j + lane) * KST + d];
#pragma unroll
            for (int i = 0; i < 8; i++)
#pragma unroll
                for (int j = 0; j < 4; j++)
                    sc[i][j] = fmaf(a[i], bv[j], sc[i][j]);
        }

        const int qg0 = qb * 64 + wrp * 8;
        const int kg_base = kb * 128;
        float alv[4];
#pragma unroll
        for (int j = 0; j < 4; j++) alv[j] = al[32 * j + lane];
#pragma unroll
        for (int i = 0; i < 8; i++) {
            const int qg = qg0 + i;
#pragma unroll
            for (int j = 0; j < 4; j++) {
                const int kg = kg_base + 32 * j + lane;
                const float sv = sc[i][j] + alv[j];
                sc[i][j] = (kg > qg) ? -1e30f : sv;
            }
        }

#pragma unroll
        for (int i = 0; i < 8; i++) {
            float mx = fmaxf(fmaxf(sc[i][0], sc[i][1]), fmaxf(sc[i][2], sc[i][3]));
#pragma unroll
            for (int off = 16; off >= 1; off >>= 1)
                mx = fmaxf(mx, __shfl_xor_sync(0xffffffffu, mx, off));
            const float mnew = fmaxf(m_run[i], mx);
            const float alpha = __expf(m_run[i] - mnew);
            float ls = 0.0f;
#pragma unroll
            for (int j = 0; j < 4; j++) {
                const float p = __expf(sc[i][j] - mnew);
                sc[i][j] = p;
                ls += p;
            }
#pragma unroll
            for (int off = 16; off >= 1; off >>= 1)
                ls += __shfl_xor_sync(0xffffffffu, ls, off);
            l_run[i] = l_run[i] * alpha + ls;
            m_run[i] = mnew;
#pragma unroll
            for (int j = 0; j < 4; j++) o[i][j] *= alpha;
#pragma unroll
            for (int j = 0; j < 4; j++)
                Ps[(wrp * 8 + i) * PST + 32 * j + lane] = sc[i][j];
        }
        __syncthreads();

#pragma unroll 4
        for (int kc = 0; kc < 128; kc++) {
            float p[8], vv[4];
#pragma unroll
            for (int i = 0; i < 8; i++) p[i] = Ps[(wrp * 8 + i) * PST + kc];
#pragma unroll
            for (int j = 0; j < 4; j++) vv[j] = Vs[kc * VST + 32 * j + lane];
#pragma unroll
            for (int i = 0; i < 8; i++)
#pragma unroll
                for (int j = 0; j < 4; j++)
                    o[i][j] = fmaf(p[i], vv[j], o[i][j]);
        }
    }

#pragma unroll
    for (int i = 0; i < 8; i++) {
        const int s_ = qb * 64 + wrp * 8 + i;
        const float invl = 1.0f / l_run[i];
        float* op = g_ctx + ((size_t)b_ * SS + s_) * HH + nh * HDD;
#pragma unroll
        for (int j = 0; j < 4; j++)
            op[32 * j + lane] = o[i][j] * invl;
    }
}

// ====================================================================
extern "C" void kernel_launch(void* const* d_in, const int* in_sizes, int n_in,
                              void* d_out, int out_size)
{
    (void)in_sizes; (void)n_in; (void)out_size;
    const float* hidden   = (const float*)d_in[0];
    const float* residual = (const float*)d_in[1];
    const float* alibi    = (const float*)d_in[2];
    // d_in[3] = attention_mask (causal; handled analytically)
    const float* W_qkv    = (const float*)d_in[4];
    const float* b_qkv    = (const float*)d_in[5];
    const float* W_dense  = (const float*)d_in[6];
    const float* b_dense  = (const float*)d_in[7];
    float* out = (float*)d_out;

    cudaFuncSetAttribute(hgemm_kernel<0>, cudaFuncAttributeMaxDynamicSharedMemorySize, GSM_TOTAL);
    cudaFuncSetAttribute(hgemm_kernel<1>, cudaFuncAttributeMaxDynamicSharedMemorySize, GSM_TOTAL);
    cudaFuncSetAttribute(attn_kernel, cudaFuncAttributeMaxDynamicSharedMemorySize, ATT_SMEM);

    convert_kernel<0><<<16384, 256>>>(hidden);    // hidden  -> A2 [hi|lo]
    convert_kernel<1><<<49152, 256>>>(W_qkv);     // W_qkv   -> W2
    convert_kernel<2><<<16384, 256>>>(W_dense);   // W_dense -> Wd2
    hgemm_kernel<0><<<3072, 256, GSM_TOTAL>>>(b_qkv, nullptr, nullptr);     // QKV
    attn_kernel<<<dim3(32, 64), 256, ATT_SMEM>>>(alibi);
    convert_kernel<3><<<16384, 256>>>(nullptr);   // ctx -> C2
    hgemm_kernel<1><<<1024, 256, GSM_TOTAL>>>(b_dense, residual, out);      // dense
}

// round 6
// speedup vs baseline: 1.9092x; 1.1823x over previous
#include <cuda_runtime.h>
#include <cuda_bf16.h>
#include <cstdint>

#define SS 2048
#define HH 4096
#define NHH 32
#define HDD 128
#define K2 8192
#define INV_NORM 0.088388347648318447f   // 1/sqrt(128)

// ---------------- scratch (__device__ globals; no allocs allowed) ----------------
__device__ __nv_bfloat16 g_qhi[16777216];   // [B,NH,S,HD] (pre-scaled by INV_NORM)
__device__ __nv_bfloat16 g_qlo[16777216];
__device__ __nv_bfloat16 g_khi[16777216];
__device__ __nv_bfloat16 g_klo[16777216];
__device__ __nv_bfloat16 g_vhi[16777216];
__device__ __nv_bfloat16 g_vlo[16777216];
__device__ __nv_bfloat16 g_A2[(size_t)4096 * K2];    // hidden  [hi|lo]
__device__ __nv_bfloat16 g_W2[(size_t)12288 * K2];   // W_qkv   [hi|lo]
__device__ __nv_bfloat16 g_Wd2[(size_t)4096 * K2];   // W_dense [hi|lo]
__device__ __nv_bfloat16 g_C2[(size_t)4096 * K2];    // ctx     [hi|lo]

// ---------------- PTX helpers ----------------
__device__ __forceinline__ uint32_t smem_u32(const void* p) {
    uint32_t a;
    asm("{ .reg .u64 t; cvta.to.shared.u64 t, %1; cvt.u32.u64 %0, t; }" : "=r"(a) : "l"(p));
    return a;
}
#define CP_ASYNC16(dst, src) \
    asm volatile("cp.async.cg.shared.global [%0], [%1], 16;" :: "r"(dst), "l"(src))
#define CP_COMMIT() asm volatile("cp.async.commit_group;" ::: "memory")
#define CP_WAIT1()  asm volatile("cp.async.wait_group 1;" ::: "memory")
#define CP_WAIT0()  asm volatile("cp.async.wait_group 0;" ::: "memory")

__device__ __forceinline__ void ldsm4(uint32_t* r, uint32_t addr) {
    asm volatile("ldmatrix.sync.aligned.m8n8.x4.shared.b16 {%0,%1,%2,%3}, [%4];"
        : "=r"(r[0]), "=r"(r[1]), "=r"(r[2]), "=r"(r[3]) : "r"(addr));
}
__device__ __forceinline__ void ldsm4t(uint32_t* r, uint32_t addr) {
    asm volatile("ldmatrix.sync.aligned.m8n8.x4.trans.shared.b16 {%0,%1,%2,%3}, [%4];"
        : "=r"(r[0]), "=r"(r[1]), "=r"(r[2]), "=r"(r[3]) : "r"(addr));
}
__device__ __forceinline__ void mma16816(float* c, const uint32_t* a, const uint32_t* b) {
    asm volatile(
        "mma.sync.aligned.m16n8k16.row.col.f32.bf16.bf16.f32 "
        "{%0,%1,%2,%3}, {%4,%5,%6,%7}, {%8,%9}, {%0,%1,%2,%3};"
        : "+f"(c[0]), "+f"(c[1]), "+f"(c[2]), "+f"(c[3])
        : "r"(a[0]), "r"(a[1]), "r"(a[2]), "r"(a[3]), "r"(b[0]), "r"(b[1]));
}
__device__ __forceinline__ uint32_t pack_bf16(__nv_bfloat16 a, __nv_bfloat16 b) {
    return (uint32_t)__bfloat16_as_ushort(a) | ((uint32_t)__bfloat16_as_ushort(b) << 16);
}

// ====================================================================
// fp32 [R][4096] -> bf16 [R][8192] as [hi | lo]
// ====================================================================
template<int WHICH>
__global__ void convert_kernel(const float* __restrict__ src) {
    size_t i = (size_t)blockIdx.x * 256 + threadIdx.x;  // one float4 per thread
    size_t r = i >> 10;
    int c = (int)(i & 1023) * 4;
    float4 v = *(const float4*)(src + (r << 12) + c);
    float f[4] = {v.x, v.y, v.z, v.w};
    unsigned short h[4], l[4];
#pragma unroll
    for (int j = 0; j < 4; j++) {
        __nv_bfloat16 hb = __float2bfloat16(f[j]);
        __nv_bfloat16 lb = __float2bfloat16(f[j] - __bfloat162float(hb));
        h[j] = __bfloat16_as_ushort(hb);
        l[j] = __bfloat16_as_ushort(lb);
    }
    uint2 hp = make_uint2((uint32_t)h[0] | ((uint32_t)h[1] << 16),
                          (uint32_t)h[2] | ((uint32_t)h[3] << 16));
    uint2 lp = make_uint2((uint32_t)l[0] | ((uint32_t)l[1] << 16),
                          (uint32_t)l[2] | ((uint32_t)l[3] << 16));
    __nv_bfloat16* dst = (WHICH == 0) ? g_A2 : (WHICH == 1) ? g_W2 : g_Wd2;
    __nv_bfloat16* base = dst + r * K2 + c;
    *(uint2*)(base) = hp;
    *(uint2*)(base + 4096) = lp;
}

// ====================================================================
// mma.sync bf16 GEMM with 3-term compensation via chunk remap (as R4).
// MODE 0: scatter (+bias) to bf16 q/k/v hi+lo
// MODE 1: out = acc + bias + residual
// ====================================================================
#define ROWB 144
#define TILEB (128 * ROWB)
#define GSM_TOTAL (4 * TILEB)
#define NCH 192

__device__ __forceinline__ void load_chunk(uint32_t sbuf,
    const __nv_bfloat16* Abase, const __nv_bfloat16* Wbase,
    int ak, int wk, int tid)
{
    const int row = tid >> 1;
    const int half = tid & 1;
    const __nv_bfloat16* asrc = Abase + (size_t)row * K2 + ak * 64 + half * 32;
    const uint32_t adst = sbuf + row * ROWB + half * 64;
#pragma unroll
    for (int i = 0; i < 4; i++) CP_ASYNC16(adst + i * 16, asrc + i * 8);
    const __nv_bfloat16* wsrc = Wbase + (size_t)row * K2 + wk * 64 + half * 32;
    const uint32_t wdst = sbuf + TILEB + row * ROWB + half * 64;
#pragma unroll
    for (int i = 0; i < 4; i++) CP_ASYNC16(wdst + i * 16, wsrc + i * 8);
}

template<int MODE>
__global__ __launch_bounds__(256) void hgemm_kernel(
    const float* __restrict__ bias, const float* __restrict__ residual,
    float* __restrict__ out)
{
    extern __shared__ char smem[];
    const uint32_t sb = smem_u32(smem);
    const int tid = threadIdx.x;
    const int wid = tid >> 5;
    const int lane = tid & 31;
    const int wm = (wid >> 2) * 64;
    const int wn = (wid & 3) * 32;

    const int id = blockIdx.x;
    const int g = id >> 7;
    const int inner = id & 127;
    const int mg = g & 1;
    const int ng = g >> 1;
    const int bm = (mg * 16 + (inner & 15)) * 128;
    const int bn = (ng * 8 + (inner >> 4)) * 128;

    const __nv_bfloat16* Abase = ((MODE == 0) ? g_A2 : g_C2) + (size_t)bm * K2;
    const __nv_bfloat16* Wbase = ((MODE == 0) ? g_W2 : g_Wd2) + (size_t)bn * K2;

    float acc[4][4][4];
#pragma unroll
    for (int mt = 0; mt < 4; mt++)
#pragma unroll
        for (int nt = 0; nt < 4; nt++)
#pragma unroll
            for (int r = 0; r < 4; r++) acc[mt][nt][r] = 0.0f;

    load_chunk(sb, Abase, Wbase, 0, 0, tid); CP_COMMIT();
    load_chunk(sb + 2 * TILEB, Abase, Wbase, 1, 1, tid); CP_COMMIT();

#pragma unroll 1
    for (int c = 0; c < NCH; c++) {
        if (c == NCH - 1) { CP_WAIT0(); } else { CP_WAIT1(); }
        __syncthreads();

        const uint32_t abuf = sb + (c & 1) * 2 * TILEB;
        const uint32_t bbuf = abuf + TILEB;
#pragma unroll
        for (int ks = 0; ks < 4; ks++) {
            uint32_t afr[4][4], bfr[2][4];
#pragma unroll
            for (int mt = 0; mt < 4; mt++) {
                const uint32_t addr = abuf +
                    (wm + mt * 16 + ((lane >> 3) & 1) * 8 + (lane & 7)) * ROWB +
                    ks * 32 + ((lane >> 4) & 1) * 16;
                ldsm4(afr[mt], addr);
            }
#pragma unroll
            for (int bi = 0; bi < 2; bi++) {
                const uint32_t addr = bbuf +
                    (wn + bi * 16 + ((lane >> 4) & 1) * 8 + (lane & 7)) * ROWB +
                    ks * 32 + ((lane >> 3) & 1) * 16;
                ldsm4(bfr[bi], addr);
            }
#pragma unroll
            for (int mt = 0; mt < 4; mt++)
#pragma unroll
                for (int nt = 0; nt < 4; nt++)
                    mma16816(acc[mt][nt], afr[mt], &bfr[nt >> 1][(nt & 1) * 2]);
        }
        __syncthreads();

        const int cc = c + 2;
        if (cc < NCH) {
            const int ak = cc & 127;
            const int wk = (cc < 64) ? cc : cc - 64;
            load_chunk(sb + (c & 1) * 2 * TILEB, Abase, Wbase, ak, wk, tid);
            CP_COMMIT();
        }
    }

    const int gq = lane >> 2;
    const int tq = lane & 3;
    if (MODE == 0) {
        const int sec = (bn >> 7) % 3;       // 0=q,1=k,2=v
        const int nh = bn / 384;
        const float scale = (sec == 0) ? INV_NORM : 1.0f;
        __nv_bfloat16* dhi = (sec == 0) ? g_qhi : (sec == 1) ? g_khi : g_vhi;
        __nv_bfloat16* dlo = (sec == 0) ? g_qlo : (sec == 1) ? g_klo : g_vlo;
#pragma unroll
        for (int mt = 0; mt < 4; mt++) {
            const int m0 = bm + wm + mt * 16 + gq;
#pragma unroll
            for (int nt = 0; nt < 4; nt++) {
                const int d = wn + nt * 8 + tq * 2;
                const float2 bv = *(const float2*)(bias + bn + d);
#pragma unroll
                for (int half = 0; half < 2; half++) {
                    const int m = m0 + half * 8;
                    const int b_ = m >> 11, s_ = m & 2047;
                    const size_t idx = (((size_t)(b_ * NHH + nh) * SS + s_) << 7) + d;
                    float v0 = (acc[mt][nt][half * 2 + 0] + bv.x) * scale;
                    float v1 = (acc[mt][nt][half * 2 + 1] + bv.y) * scale;
                    __nv_bfloat16 h0 = __float2bfloat16(v0);
                    __nv_bfloat16 h1 = __float2bfloat16(v1);
                    __nv_bfloat16 l0 = __float2bfloat16(v0 - __bfloat162float(h0));
                    __nv_bfloat16 l1 = __float2bfloat16(v1 - __bfloat162float(h1));
                    *(uint32_t*)(dhi + idx) = pack_bf16(h0, h1);
                    *(uint32_t*)(dlo + idx) = pack_bf16(l0, l1);
                }
            }
        }
    } else {
#pragma unroll
        for (int mt = 0; mt < 4; mt++) {
            const int m0 = bm + wm + mt * 16 + gq;
#pragma unroll
            for (int nt = 0; nt < 4; nt++) {
                const int n0 = bn + wn + nt * 8 + tq * 2;
                const float2 bv = *(const float2*)(bias + n0);
                {
                    const size_t i0 = (size_t)m0 * HH + n0;
                    const float2 rv = *(const float2*)(residual + i0);
                    *(float2*)(out + i0) = make_float2(acc[mt][nt][0] + bv.x + rv.x,
                                                       acc[mt][nt][1] + bv.y + rv.y);
                }
                {
                    const size_t i1 = (size_t)(m0 + 8) * HH + n0;
                    const float2 rv = *(const float2*)(residual + i1);
                    *(float2*)(out + i1) = make_float2(acc[mt][nt][2] + bv.x + rv.x,
                                                       acc[mt][nt][3] + bv.y + rv.y);
                }
            }
        }
    }
}

// ====================================================================
// Tensor-core causal flash attention with ALiBi — fully compensated.
// QK^T: Qhi·Khi + Qlo·Khi + Qhi·Klo.  PV: Phi·Vhi + Plo·Vhi + Phi·Vlo
// with P split hi/lo in registers per k-chunk. l sums fp32 p.
// CTA: 128 q-rows (8 warps x m16), k-blocks of 64, cp.async dbl-buffered.
// ====================================================================
#define ATROW 272                       // 128 bf16 + 8 pad = 272 bytes
#define SQ_HI 0
#define SQ_LO (128 * ATROW)             // 34816
#define SBUF0 (2 * 128 * ATROW)         // 69632
#define SK_HI 0
#define SK_LO (64 * ATROW)
#define SV_HI (2 * 64 * ATROW)
#define SV_LO (3 * 64 * ATROW)
#define SBUF_SZ (4 * 64 * ATROW)        // 69632
#define ATT_SMEM (SBUF0 + 2 * SBUF_SZ)  // 208896

__device__ __forceinline__ void attn_load_kv(uint32_t sbuf, int bh, int kb, int tid)
{
    const int row = tid >> 2;           // 0..63
    const int off = (tid & 3) * 64;     // byte offset
    const size_t gidx = ((size_t)bh * SS + (size_t)kb * 64 + row) * HDD + (off >> 1);
    const uint32_t dbase = sbuf + row * ATROW + off;
#pragma unroll
    for (int i = 0; i < 4; i++) CP_ASYNC16(dbase + SK_HI + i * 16, g_khi + gidx + i * 8);
#pragma unroll
    for (int i = 0; i < 4; i++) CP_ASYNC16(dbase + SK_LO + i * 16, g_klo + gidx + i * 8);
#pragma unroll
    for (int i = 0; i < 4; i++) CP_ASYNC16(dbase + SV_HI + i * 16, g_vhi + gidx + i * 8);
#pragma unroll
    for (int i = 0; i < 4; i++) CP_ASYNC16(dbase + SV_LO + i * 16, g_vlo + gidx + i * 8);
}

__global__ __launch_bounds__(256) void attn_kernel(const float* __restrict__ alibi)
{
    extern __shared__ char smem[];
    const uint32_t sb = smem_u32(smem);
    const int tid = threadIdx.x;
    const int lane = tid & 31;
    const int wid = tid >> 5;
    const int wq = wid * 16;
    const int qb = (int)gridDim.x - 1 - (int)blockIdx.x;   // heavy CTAs first
    const int bh = blockIdx.y;
    const int b_ = bh >> 5;
    const int nh = bh & 31;

    const float* alrow = alibi + (size_t)bh * SS;

    // load Q tile (hi+lo), 128 rows x 256B
    {
        const int row = tid >> 1;
        const int off = (tid & 1) * 128;
        const size_t gidx = ((size_t)bh * SS + (size_t)qb * 128 + row) * HDD + (off >> 1);
        const uint32_t dq = sb + row * ATROW + off;
#pragma unroll
        for (int i = 0; i < 8; i++) CP_ASYNC16(dq + SQ_HI + i * 16, g_qhi + gidx + i * 8);
#pragma unroll
        for (int i = 0; i < 8; i++) CP_ASYNC16(dq + SQ_LO + i * 16, g_qlo + gidx + i * 8);
    }
    attn_load_kv(sb + SBUF0, bh, 0, tid);
    CP_COMMIT();

    const int kbmax = 2 * qb + 1;
    float m0 = -1e30f, m1 = -1e30f, l0 = 0.0f, l1 = 0.0f;
    float acc[16][4];
#pragma unroll
    for (int nt = 0; nt < 16; nt++)
#pragma unroll
        for (int r = 0; r < 4; r++) acc[nt][r] = 0.0f;

    const int gq = lane >> 2, tq = lane & 3;
    const int q0 = qb * 128 + wq + gq;
    const int q1 = q0 + 8;

#pragma unroll 1
    for (int kb = 0; kb <= kbmax; kb++) {
        if (kb < kbmax) {
            attn_load_kv(sb + SBUF0 + ((kb + 1) & 1) * SBUF_SZ, bh, kb + 1, tid);
            CP_COMMIT();
            CP_WAIT1();
        } else {
            CP_WAIT0();
        }
        __syncthreads();

        const uint32_t kbuf = sb + SBUF0 + (kb & 1) * SBUF_SZ;

        // ---- QK^T (compensated) ----
        float cs[8][4];
#pragma unroll
        for (int nt = 0; nt < 8; nt++)
#pragma unroll
            for (int r = 0; r < 4; r++) cs[nt][r] = 0.0f;

#pragma unroll
        for (int ks = 0; ks < 8; ks++) {
            uint32_t ah[4], alr[4];
            const uint32_t aaddr = sb +
                (wq + ((lane >> 3) & 1) * 8 + (lane & 7)) * ATROW +
                ks * 32 + ((lane >> 4) & 1) * 16;
            ldsm4(ah, aaddr + SQ_HI);
            ldsm4(alr, aaddr + SQ_LO);
#pragma unroll
            for (int g = 0; g < 4; g++) {
                uint32_t kh[4], kl[4];
                const uint32_t baddr = kbuf +
                    (g * 16 + ((lane >> 4) & 1) * 8 + (lane & 7)) * ATROW +
                    ks * 32 + ((lane >> 3) & 1) * 16;
                ldsm4(kh, baddr + SK_HI);
                ldsm4(kl, baddr + SK_LO);
                mma16816(cs[g * 2], ah, kh);
                mma16816(cs[g * 2], alr, kh);
                mma16816(cs[g * 2], ah, kl);
                mma16816(cs[g * 2 + 1], ah, kh + 2);
                mma16816(cs[g * 2 + 1], alr, kh + 2);
                mma16816(cs[g * 2 + 1], ah, kl + 2);
            }
        }

        // ---- alibi + causal mask ----
        const bool domask = (kb * 64 + 63 > qb * 128 + wq);
#pragma unroll
        for (int nt = 0; nt < 8; nt++) {
            const int kcol = kb * 64 + nt * 8 + tq * 2;
            const float2 av = *(const float2*)(alrow + kcol);
            cs[nt][0] += av.x; cs[nt][1] += av.y;
            cs[nt][2] += av.x; cs[nt][3] += av.y;
            if (domask) {
                if (kcol > q0)     cs[nt][0] = -1e30f;
                if (kcol + 1 > q0) cs[nt][1] = -1e30f;
                if (kcol > q1)     cs[nt][2] = -1e30f;
                if (kcol + 1 > q1) cs[nt][3] = -1e30f;
            }
        }

        // ---- online softmax (2 rows per lane); cs becomes fp32 P ----
        float mx0 = -1e30f, mx1 = -1e30f;
#pragma unroll
        for (int nt = 0; nt < 8; nt++) {
            mx0 = fmaxf(mx0, fmaxf(cs[nt][0], cs[nt][1]));
            mx1 = fmaxf(mx1, fmaxf(cs[nt][2], cs[nt][3]));
        }
        mx0 = fmaxf(mx0, __shfl_xor_sync(0xffffffffu, mx0, 1));
        mx0 = fmaxf(mx0, __shfl_xor_sync(0xffffffffu, mx0, 2));
        mx1 = fmaxf(mx1, __shfl_xor_sync(0xffffffffu, mx1, 1));
        mx1 = fmaxf(mx1, __shfl_xor_sync(0xffffffffu, mx1, 2));
        const float mn0 = fmaxf(m0, mx0);
        const float mn1 = fmaxf(m1, mx1);
        const float a0 = __expf(m0 - mn0);
        const float a1 = __expf(m1 - mn1);
        m0 = mn0; m1 = mn1;
        l0 *= a0; l1 *= a1;
#pragma unroll
        for (int nt = 0; nt < 16; nt++) {
            acc[nt][0] *= a0; acc[nt][1] *= a0;
            acc[nt][2] *= a1; acc[nt][3] *= a1;
        }

        float ps0 = 0.0f, ps1 = 0.0f;
#pragma unroll
        for (int nt = 0; nt < 8; nt++) {
            cs[nt][0] = __expf(cs[nt][0] - mn0);
            cs[nt][1] = __expf(cs[nt][1] - mn0);
            cs[nt][2] = __expf(cs[nt][2] - mn1);
            cs[nt][3] = __expf(cs[nt][3] - mn1);
            ps0 += cs[nt][0] + cs[nt][1];
            ps1 += cs[nt][2] + cs[nt][3];
        }
        ps0 += __shfl_xor_sync(0xffffffffu, ps0, 1);
        ps0 += __shfl_xor_sync(0xffffffffu, ps0, 2);
        ps1 += __shfl_xor_sync(0xffffffffu, ps1, 1);
        ps1 += __shfl_xor_sync(0xffffffffu, ps1, 2);
        l0 += ps0; l1 += ps1;

        // ---- P @ V (compensated: Phi.Vhi + Plo.Vhi + Phi.Vlo) ----
        const int vg = lane >> 3, vr = lane & 7;
#pragma unroll
        for (int ks2 = 0; ks2 < 4; ks2++) {
            uint32_t pahi[4], palo[4];
#pragma unroll
            for (int t = 0; t < 2; t++) {
                const int nt = 2 * ks2 + t;
                const __nv_bfloat16 h0 = __float2bfloat16(cs[nt][0]);
                const __nv_bfloat16 h1 = __float2bfloat16(cs[nt][1]);
                const __nv_bfloat16 h2 = __float2bfloat16(cs[nt][2]);
                const __nv_bfloat16 h3 = __float2bfloat16(cs[nt][3]);
                pahi[2 * t]     = pack_bf16(h0, h1);
                pahi[2 * t + 1] = pack_bf16(h2, h3);
                palo[2 * t]     = pack_bf16(__float2bfloat16(cs[nt][0] - __bfloat162float(h0)),
                                            __float2bfloat16(cs[nt][1] - __bfloat162float(h1)));
                palo[2 * t + 1] = pack_bf16(__float2bfloat16(cs[nt][2] - __bfloat162float(h2)),
                                            __float2bfloat16(cs[nt][3] - __bfloat162float(h3)));
            }
            const uint32_t vrow = (ks2 * 16 + (vg & 1) * 8 + vr) * ATROW + (vg >> 1) * 16;
#pragma unroll
            for (int dg = 0; dg < 8; dg++) {
                uint32_t th[4], tl[4];
                ldsm4t(th, kbuf + SV_HI + vrow + dg * 32);
                ldsm4t(tl, kbuf + SV_LO + vrow + dg * 32);
                mma16816(acc[dg * 2], pahi, th);
                mma16816(acc[dg * 2], palo, th);
                mma16816(acc[dg * 2], pahi, tl);
                mma16816(acc[dg * 2 + 1], pahi, th + 2);
                mma16816(acc[dg * 2 + 1], palo, th + 2);
                mma16816(acc[dg * 2 + 1], pahi, tl + 2);
            }
        }
        __syncthreads();
    }

    // ---- epilogue: ctx/l -> bf16 hi/lo directly into g_C2 ----
    const float il0 = 1.0f / l0;
    const float il1 = 1.0f / l1;
    const size_t r0 = ((size_t)b_ * SS + q0) * K2 + nh * 128;
    const size_t r1 = ((size_t)b_ * SS + q1) * K2 + nh * 128;
#pragma unroll
    for (int nt = 0; nt < 16; nt++) {
        const int d = nt * 8 + tq * 2;
        const float f0 = acc[nt][0] * il0, f1 = acc[nt][1] * il0;
        const float f2 = acc[nt][2] * il1, f3 = acc[nt][3] * il1;
        const __nv_bfloat16 h0 = __float2bfloat16(f0), h1 = __float2bfloat16(f1);
        const __nv_bfloat16 h2 = __float2bfloat16(f2), h3 = __float2bfloat16(f3);
        *(uint32_t*)(g_C2 + r0 + d) = pack_bf16(h0, h1);
        *(uint32_t*)(g_C2 + r1 + d) = pack_bf16(h2, h3);
        const __nv_bfloat16 e0 = __float2bfloat16(f0 - __bfloat162float(h0));
        const __nv_bfloat16 e1 = __float2bfloat16(f1 - __bfloat162float(h1));
        const __nv_bfloat16 e2 = __float2bfloat16(f2 - __bfloat162float(h2));
        const __nv_bfloat16 e3 = __float2bfloat16(f3 - __bfloat162float(h3));
        *(uint32_t*)(g_C2 + r0 + 4096 + d) = pack_bf16(e0, e1);
        *(uint32_t*)(g_C2 + r1 + 4096 + d) = pack_bf16(e2, e3);
    }
}

// ====================================================================
extern "C" void kernel_launch(void* const* d_in, const int* in_sizes, int n_in,
                              void* d_out, int out_size)
{
    (void)in_sizes; (void)n_in; (void)out_size;
    const float* hidden   = (const float*)d_in[0];
    const float* residual = (const float*)d_in[1];
    const float* alibi    = (const float*)d_in[2];
    // d_in[3] = attention_mask (causal; handled analytically)
    const float* W_qkv    = (const float*)d_in[4];
    const float* b_qkv    = (const float*)d_in[5];
    const float* W_dense  = (const float*)d_in[6];
    const float* b_dense  = (const float*)d_in[7];
    float* out = (float*)d_out;

    cudaFuncSetAttribute(hgemm_kernel<0>, cudaFuncAttributeMaxDynamicSharedMemorySize, GSM_TOTAL);
    cudaFuncSetAttribute(hgemm_kernel<1>, cudaFuncAttributeMaxDynamicSharedMemorySize, GSM_TOTAL);
    cudaFuncSetAttribute(attn_kernel, cudaFuncAttributeMaxDynamicSharedMemorySize, ATT_SMEM);

    convert_kernel<0><<<16384, 256>>>(hidden);    // hidden  -> A2 [hi|lo]
    convert_kernel<1><<<49152, 256>>>(W_qkv);     // W_qkv   -> W2
    convert_kernel<2><<<16384, 256>>>(W_dense);   // W_dense -> Wd2
    hgemm_kernel<0><<<3072, 256, GSM_TOTAL>>>(b_qkv, nullptr, nullptr);     // QKV
    attn_kernel<<<dim3(16, 64), 256, ATT_SMEM>>>(alibi);                    // flash attn (TC)
    hgemm_kernel<1><<<1024, 256, GSM_TOTAL>>>(b_dense, residual, out);      // dense
}